// round 3
// baseline (speedup 1.0000x reference)
#include <cuda_runtime.h>
#include <cstdint>

// ---------------------------------------------------------------------------
// Problem constants
// ---------------------------------------------------------------------------
#define TOKENS   100352          // B * D*H*W = 2*16*56*56 = 1024 windows * 98
#define CDIM     512
#define QKVDIM   1536
#define MLPDIM   2048
#define NWINHEAD 16384           // 1024 windows * 16 heads

// ---------------------------------------------------------------------------
// Scratch (static device arrays; no runtime allocation allowed)
// ---------------------------------------------------------------------------
__device__ float g_h     [(size_t)TOKENS * CDIM];    // LN1 out, reused as LN2 out
__device__ float g_qkv   [(size_t)TOKENS * QKVDIM];
__device__ float g_o     [(size_t)TOKENS * CDIM];    // attention out (windowed)
__device__ float g_attn  [(size_t)TOKENS * CDIM];    // proj out (windowed) = "xr"
__device__ float g_hidden[(size_t)TOKENS * MLPDIM];

// ---------------------------------------------------------------------------
// windowed token index -> original token index
// window order: (b, nd, nh, nw), token-in-window: (dw, hw, ww)
// ---------------------------------------------------------------------------
__device__ __forceinline__ int w2o(int m) {
    int win = m / 98;
    int n   = m - win * 98;
    int b   = win >> 9;          // / 512
    int r   = win & 511;
    int wd  = r >> 6;            // / 64
    int wh  = (r >> 3) & 7;
    int ww  = r & 7;
    int dw  = n / 49;
    int rem = n - dw * 49;
    int hw  = rem / 7;
    int wl  = rem - hw * 7;
    int d  = wd * 2 + dw;
    int hh = wh * 7 + hw;
    int w  = ww * 7 + wl;
    return ((b * 16 + d) * 56 + hh) * 56 + w;
}

// ---------------------------------------------------------------------------
// LayerNorm: one warp per row of 512. gather=1: read x[w2o(row)] (window part.)
// ---------------------------------------------------------------------------
__global__ void ln_kernel(const float* __restrict__ x, const float* __restrict__ g,
                          const float* __restrict__ b, float* __restrict__ out,
                          int gather)
{
    int row  = blockIdx.x * 8 + (threadIdx.x >> 5);
    int lane = threadIdx.x & 31;
    if (row >= TOKENS) return;
    int src = gather ? w2o(row) : row;
    const float* xr = x + (size_t)src * CDIM;

    float v[16], s = 0.f, ss = 0.f;
#pragma unroll
    for (int k = 0; k < 16; ++k) {
        float a = xr[lane + 32 * k];
        v[k] = a; s += a; ss += a * a;
    }
#pragma unroll
    for (int off = 16; off; off >>= 1) {
        s  += __shfl_xor_sync(0xffffffffu, s,  off);
        ss += __shfl_xor_sync(0xffffffffu, ss, off);
    }
    float mu   = s * (1.f / 512.f);
    float var  = ss * (1.f / 512.f) - mu * mu;
    float rstd = rsqrtf(var + 1e-5f);

    float* orow = out + (size_t)row * CDIM;
#pragma unroll
    for (int k = 0; k < 16; ++k) {
        int c = lane + 32 * k;
        orow[c] = (v[k] - mu) * rstd * g[c] + b[c];
    }
}

// ---------------------------------------------------------------------------
// TF32x2 GEMM: C[M,N] = A[M,K] @ B[K,N] (+bias, +gelu, +res/scatter)
// 128x128 block tile, BK=16, 256 threads, warp grid 2x4, warp tile 64x32,
// mma.sync.m16n8k8 tf32; hi/lo split (3 mma) for ~fp32 accuracy.
// M % 128 == 0, N % 128 == 0, K % 16 == 0 (all shapes here comply).
// ---------------------------------------------------------------------------
#define GTILE  (16 * 132)                 // one smem tile in 32-bit words
#define GEMM_SMEM_BYTES (8 * GTILE * 4)   // 4 arrays x 2 buffers = 67584 B

__device__ __forceinline__ void cvt2(float x, unsigned& hi, unsigned& lo) {
    unsigned h;
    asm("cvt.rna.tf32.f32 %0, %1;" : "=r"(h) : "f"(x));
    float r = x - __uint_as_float(h);
    unsigned l;
    asm("cvt.rna.tf32.f32 %0, %1;" : "=r"(l) : "f"(r));
    hi = h; lo = l;
}

__device__ __forceinline__ void mma8(float c[4], const unsigned a[4], const unsigned b[2]) {
    asm volatile(
        "mma.sync.aligned.m16n8k8.row.col.f32.tf32.tf32.f32 "
        "{%0,%1,%2,%3},{%4,%5,%6,%7},{%8,%9},{%0,%1,%2,%3};"
        : "+f"(c[0]), "+f"(c[1]), "+f"(c[2]), "+f"(c[3])
        : "r"(a[0]), "r"(a[1]), "r"(a[2]), "r"(a[3]), "r"(b[0]), "r"(b[1]));
}

__device__ __forceinline__ float gelu_tanh(float x) {
    float u = 0.7978845608028654f * (x + 0.044715f * x * x * x);
    return 0.5f * x * (1.f + tanhf(u));
}

__device__ __forceinline__ void gemm_ldg(const float* __restrict__ A,
                                         const float* __restrict__ Bw,
                                         int K, int N, int bm, int bn, int kt, int t,
                                         float ra[8], float rb[8])
{
    const float* Ap = A + (size_t)bm * K + (size_t)kt * 16;
#pragma unroll
    for (int r = 0; r < 2; ++r) {
        int f = t + 256 * r;
        int row = f >> 2, kq = (f & 3) << 2;
        float4 v = *(const float4*)(Ap + (size_t)row * K + kq);
        ra[4*r+0] = v.x; ra[4*r+1] = v.y; ra[4*r+2] = v.z; ra[4*r+3] = v.w;
    }
    const float* Bp = Bw + (size_t)(kt * 16) * N + bn;
#pragma unroll
    for (int r = 0; r < 2; ++r) {
        int f = t + 256 * r;
        int kr = f >> 5, nq = (f & 31) << 2;
        float4 v = *(const float4*)(Bp + (size_t)kr * N + nq);
        rb[4*r+0] = v.x; rb[4*r+1] = v.y; rb[4*r+2] = v.z; rb[4*r+3] = v.w;
    }
}

__device__ __forceinline__ void gemm_sts(unsigned* ah, unsigned* al,
                                         unsigned* bh, unsigned* bl,
                                         int t, const float ra[8], const float rb[8])
{
#pragma unroll
    for (int r = 0; r < 2; ++r) {
        int f = t + 256 * r;
        int row = f >> 2, kq = (f & 3) << 2;
#pragma unroll
        for (int i = 0; i < 4; ++i) {
            unsigned h, l; cvt2(ra[4*r+i], h, l);
            ah[(kq + i) * 132 + row] = h;
            al[(kq + i) * 132 + row] = l;
        }
        int kr = f >> 5, nq = (f & 31) << 2;
#pragma unroll
        for (int i = 0; i < 4; ++i) {
            unsigned h, l; cvt2(rb[4*r+i], h, l);
            bh[kr * 132 + nq + i] = h;
            bl[kr * 132 + nq + i] = l;
        }
    }
}

__device__ __forceinline__ void gemm_compute(const unsigned* ah, const unsigned* al,
                                             const unsigned* bh, const unsigned* bl,
                                             int wm, int wn, int lane, float c[4][4][4])
{
#pragma unroll
    for (int kk = 0; kk < 16; kk += 8) {
        unsigned Ah[4][4], Al[4][4], Bh[4][2], Bl[4][2];
        int ka = kk + (lane & 3);
        int mg = lane >> 2;
#pragma unroll
        for (int i = 0; i < 4; ++i) {
            int m0 = wm * 64 + i * 16 + mg;
            Ah[i][0] = ah[ka * 132 + m0];
            Ah[i][1] = ah[ka * 132 + m0 + 8];
            Ah[i][2] = ah[(ka + 4) * 132 + m0];
            Ah[i][3] = ah[(ka + 4) * 132 + m0 + 8];
            Al[i][0] = al[ka * 132 + m0];
            Al[i][1] = al[ka * 132 + m0 + 8];
            Al[i][2] = al[(ka + 4) * 132 + m0];
            Al[i][3] = al[(ka + 4) * 132 + m0 + 8];
        }
#pragma unroll
        for (int j = 0; j < 4; ++j) {
            int n0 = wn * 32 + j * 8 + mg;
            Bh[j][0] = bh[ka * 132 + n0];
            Bh[j][1] = bh[(ka + 4) * 132 + n0];
            Bl[j][0] = bl[ka * 132 + n0];
            Bl[j][1] = bl[(ka + 4) * 132 + n0];
        }
#pragma unroll
        for (int i = 0; i < 4; ++i)
#pragma unroll
            for (int j = 0; j < 4; ++j) {
                mma8(c[i][j], Ah[i], Bh[j]);
                mma8(c[i][j], Ah[i], Bl[j]);
                mma8(c[i][j], Al[i], Bh[j]);
            }
    }
}

// EPI: 0 = +bias ; 1 = +bias,gelu ; 2 = +bias,+res, scatter rows via w2o (N==512)
template <int EPI>
__global__ void __launch_bounds__(256, 1)
gemm_tf32x2(const float* __restrict__ A, const float* __restrict__ Bw,
            const float* __restrict__ bias, const float* __restrict__ res,
            float* __restrict__ Cm, int M, int N, int K)
{
    extern __shared__ unsigned smem_u[];
    unsigned* sAhi = smem_u;
    unsigned* sAlo = smem_u + 2 * GTILE;
    unsigned* sBhi = smem_u + 4 * GTILE;
    unsigned* sBlo = smem_u + 6 * GTILE;

    int t = threadIdx.x;
    int warp = t >> 5, lane = t & 31;
    int wm = warp >> 2, wn = warp & 3;
    int bm = blockIdx.y * 128, bn = blockIdx.x * 128;

    float c[4][4][4];
#pragma unroll
    for (int i = 0; i < 4; ++i)
#pragma unroll
        for (int j = 0; j < 4; ++j)
#pragma unroll
            for (int k = 0; k < 4; ++k) c[i][j][k] = 0.f;

    float ra[8], rb[8];
    gemm_ldg(A, Bw, K, N, bm, bn, 0, t, ra, rb);
    gemm_sts(sAhi, sAlo, sBhi, sBlo, t, ra, rb);
    __syncthreads();

    int KT = K >> 4;
    for (int kt = 0; kt < KT; ++kt) {
        int cur = kt & 1;
        if (kt + 1 < KT) gemm_ldg(A, Bw, K, N, bm, bn, kt + 1, t, ra, rb);
        gemm_compute(sAhi + cur * GTILE, sAlo + cur * GTILE,
                     sBhi + cur * GTILE, sBlo + cur * GTILE, wm, wn, lane, c);
        if (kt + 1 < KT) {
            int nxt = cur ^ 1;
            gemm_sts(sAhi + nxt * GTILE, sAlo + nxt * GTILE,
                     sBhi + nxt * GTILE, sBlo + nxt * GTILE, t, ra, rb);
        }
        __syncthreads();
    }

    // epilogue
#pragma unroll
    for (int i = 0; i < 4; ++i) {
        int r0 = bm + wm * 64 + i * 16 + (lane >> 2);
        int rows[2] = { r0, r0 + 8 };
        int dst[2];
        if (EPI == 2) { dst[0] = w2o(rows[0]); dst[1] = w2o(rows[1]); }
#pragma unroll
        for (int j = 0; j < 4; ++j) {
            int col = bn + wn * 32 + j * 8 + ((lane & 3) << 1);
            float bv0 = bias[col], bv1 = bias[col + 1];
#pragma unroll
            for (int rr = 0; rr < 2; ++rr) {
                float v0 = c[i][j][rr * 2 + 0] + bv0;
                float v1 = c[i][j][rr * 2 + 1] + bv1;
                if (EPI == 1) { v0 = gelu_tanh(v0); v1 = gelu_tanh(v1); }
                if (EPI == 2) {
                    size_t ro = (size_t)rows[rr] * CDIM + col;
                    v0 += res[ro]; v1 += res[ro + 1];
                    size_t oo = (size_t)dst[rr] * CDIM + col;
                    Cm[oo] = v0; Cm[oo + 1] = v1;
                } else {
                    size_t oo = (size_t)rows[rr] * (size_t)N + col;
                    Cm[oo] = v0; Cm[oo + 1] = v1;
                }
            }
        }
    }
}

// ---------------------------------------------------------------------------
// Windowed attention: one CTA per (window, head). 128 threads.
// smem: Q[98][32], K[98][36] (pad), Vt[32][100] (transposed, pad), P[98][100]
// ---------------------------------------------------------------------------
#define SQ_OFF  0
#define SK_OFF  3136
#define SVT_OFF (3136 + 3528)
#define SP_OFF  (SVT_OFF + 3200)
#define ATTN_SMEM_BYTES ((SP_OFF + 9800) * 4)   // 78656 B

__global__ void __launch_bounds__(128)
attn_kernel(const float* __restrict__ qkv, float* __restrict__ o)
{
    extern __shared__ float sm[];
    float* sQ  = sm + SQ_OFF;
    float* sK  = sm + SK_OFF;
    float* sVt = sm + SVT_OFF;
    float* sP  = sm + SP_OFF;

    int win  = blockIdx.x >> 4;
    int head = blockIdx.x & 15;
    int t = threadIdx.x, warp = t >> 5, lane = t & 31;

    // zero Vt pad columns (98,99) — disjoint from loaded region, no race
    if (t < 64) sVt[(t >> 1) * 100 + 98 + (t & 1)] = 0.f;

    const float scale = 0.17677669529663687f;   // 1/sqrt(32)
    size_t base = (size_t)win * 98 * QKVDIM + (size_t)head * 32;
    for (int idx = t; idx < 98 * 32; idx += 128) {
        int n = idx >> 5, hd = idx & 31;
        const float* p = qkv + base + (size_t)n * QKVDIM + hd;
        sQ[n * 32 + hd]   = p[0] * scale;
        sK[n * 36 + hd]   = p[512];
        sVt[hd * 100 + n] = p[1024];
    }
    __syncthreads();

    // scores + softmax, one warp per row (strided)
    for (int i = warp; i < 98; i += 4) {
        float4 q4[8];
        const float4* qrow = (const float4*)(sQ + i * 32);
#pragma unroll
        for (int cc = 0; cc < 8; ++cc) q4[cc] = qrow[cc];

        float sv[4];
        float mx = -1e30f;
#pragma unroll
        for (int jj = 0; jj < 4; ++jj) {
            int j = lane + jj * 32;
            float a = -1e30f;
            if (j < 98) {
                const float4* krow = (const float4*)(sK + j * 36);
                float acc = 0.f;
#pragma unroll
                for (int cc = 0; cc < 8; ++cc) {
                    float4 k4 = krow[cc];
                    acc += q4[cc].x * k4.x + q4[cc].y * k4.y
                         + q4[cc].z * k4.z + q4[cc].w * k4.w;
                }
                a = acc;
            }
            sv[jj] = a;
            mx = fmaxf(mx, a);
        }
#pragma unroll
        for (int off = 16; off; off >>= 1)
            mx = fmaxf(mx, __shfl_xor_sync(0xffffffffu, mx, off));
        float sum = 0.f;
#pragma unroll
        for (int jj = 0; jj < 4; ++jj) {
            int j = lane + jj * 32;
            float e = (j < 98) ? __expf(sv[jj] - mx) : 0.f;
            sv[jj] = e; sum += e;
        }
#pragma unroll
        for (int off = 16; off; off >>= 1)
            sum += __shfl_xor_sync(0xffffffffu, sum, off);
        float inv = 1.f / sum;
#pragma unroll
        for (int jj = 0; jj < 4; ++jj) {
            int j = lane + jj * 32;
            if (j < 98) sP[i * 100 + j] = sv[jj] * inv;
        }
        if (lane < 2) sP[i * 100 + 98 + lane] = 0.f;
    }
    __syncthreads();

    // O = P @ V : thread -> (row i, hd = lane)
    size_t obase = (size_t)win * 98 * CDIM + (size_t)head * 32 + lane;
    const float4* vrow = (const float4*)(sVt + lane * 100);
    for (int i = warp; i < 98; i += 4) {
        const float4* prow = (const float4*)(sP + i * 100);
        float acc = 0.f;
#pragma unroll
        for (int cc = 0; cc < 25; ++cc) {
            float4 p4 = prow[cc];
            float4 v4 = vrow[cc];
            acc += p4.x * v4.x + p4.y * v4.y + p4.z * v4.z + p4.w * v4.w;
        }
        o[obase + (size_t)i * CDIM] = acc;
    }
}

// ---------------------------------------------------------------------------
// launch
// ---------------------------------------------------------------------------
extern "C" void kernel_launch(void* const* d_in, const int* in_sizes, int n_in,
                              void* d_out, int out_size)
{
    (void)in_sizes; (void)n_in; (void)out_size;

    const float* x     = (const float*)d_in[0];
    const float* g1    = (const float*)d_in[1];
    const float* b1    = (const float*)d_in[2];
    const float* wqkv  = (const float*)d_in[3];
    const float* bqkv  = (const float*)d_in[4];
    const float* wproj = (const float*)d_in[5];
    const float* bproj = (const float*)d_in[6];
    const float* g2    = (const float*)d_in[7];
    const float* b2    = (const float*)d_in[8];
    const float* w1    = (const float*)d_in[9];
    const float* bm1   = (const float*)d_in[10];
    const float* w2    = (const float*)d_in[11];
    const float* bm2   = (const float*)d_in[12];
    float* out = (float*)d_out;

    float *h, *qkv, *o, *attn, *hidden;
    cudaGetSymbolAddress((void**)&h,      g_h);
    cudaGetSymbolAddress((void**)&qkv,    g_qkv);
    cudaGetSymbolAddress((void**)&o,      g_o);
    cudaGetSymbolAddress((void**)&attn,   g_attn);
    cudaGetSymbolAddress((void**)&hidden, g_hidden);

    cudaFuncSetAttribute((const void*)gemm_tf32x2<0>,
                         cudaFuncAttributeMaxDynamicSharedMemorySize, GEMM_SMEM_BYTES);
    cudaFuncSetAttribute((const void*)gemm_tf32x2<1>,
                         cudaFuncAttributeMaxDynamicSharedMemorySize, GEMM_SMEM_BYTES);
    cudaFuncSetAttribute((const void*)gemm_tf32x2<2>,
                         cudaFuncAttributeMaxDynamicSharedMemorySize, GEMM_SMEM_BYTES);
    cudaFuncSetAttribute((const void*)attn_kernel,
                         cudaFuncAttributeMaxDynamicSharedMemorySize, ATTN_SMEM_BYTES);

    const int LN_BLOCKS = TOKENS / 8;   // 12544, 8 warps/block

    // 1. window-partition gather + LN1 -> h (windowed)
    ln_kernel<<<LN_BLOCKS, 256>>>(x, g1, b1, h, 1);

    // 2. qkv = h @ wqkv + bqkv
    gemm_tf32x2<0><<<dim3(QKVDIM / 128, TOKENS / 128), 256, GEMM_SMEM_BYTES>>>(
        h, wqkv, bqkv, nullptr, qkv, TOKENS, QKVDIM, CDIM);

    // 3. windowed attention -> o (windowed, head-merged)
    attn_kernel<<<NWINHEAD, 128, ATTN_SMEM_BYTES>>>(qkv, o);

    // 4. attn = o @ wproj + bproj (stays windowed)
    gemm_tf32x2<0><<<dim3(CDIM / 128, TOKENS / 128), 256, GEMM_SMEM_BYTES>>>(
        o, wproj, bproj, nullptr, attn, TOKENS, CDIM, CDIM);

    // 5. LN2 -> h (reuse)
    ln_kernel<<<LN_BLOCKS, 256>>>(attn, g2, b2, h, 0);

    // 6. hidden = gelu(h @ w1 + bm1)
    gemm_tf32x2<1><<<dim3(MLPDIM / 128, TOKENS / 128), 256, GEMM_SMEM_BYTES>>>(
        h, w1, bm1, nullptr, hidden, TOKENS, MLPDIM, CDIM);

    // 7. out[w2o(m)] = attn[m] + hidden[m] @ w2 + bm2  (window reverse fused)
    gemm_tf32x2<2><<<dim3(CDIM / 128, TOKENS / 128), 256, GEMM_SMEM_BYTES>>>(
        hidden, w2, bm2, attn, out, TOKENS, CDIM, MLPDIM);
}

// round 4
// speedup vs baseline: 1.6546x; 1.6546x over previous
#include <cuda_runtime.h>
#include <cstdint>

// ---------------------------------------------------------------------------
// Problem constants
// ---------------------------------------------------------------------------
#define TOKENS   100352          // B * D*H*W = 2*16*56*56 = 1024 windows * 98
#define CDIM     512
#define QKVDIM   1536
#define MLPDIM   2048
#define NWINHEAD 16384           // 1024 windows * 16 heads

// ---------------------------------------------------------------------------
// Scratch (static device arrays; no runtime allocation allowed)
// ---------------------------------------------------------------------------
__device__ float g_h     [(size_t)TOKENS * CDIM];    // LN1 out, reused as LN2 out
__device__ float g_qkv   [(size_t)TOKENS * QKVDIM];
__device__ float g_o     [(size_t)TOKENS * CDIM];    // attention out (windowed)
__device__ float g_attn  [(size_t)TOKENS * CDIM];    // proj out (windowed) = "xr"
__device__ float g_hidden[(size_t)TOKENS * MLPDIM];

// ---------------------------------------------------------------------------
// windowed token index -> original token index
// ---------------------------------------------------------------------------
__device__ __forceinline__ int w2o(int m) {
    int win = m / 98;
    int n   = m - win * 98;
    int b   = win >> 9;
    int r   = win & 511;
    int wd  = r >> 6;
    int wh  = (r >> 3) & 7;
    int ww  = r & 7;
    int dw  = n / 49;
    int rem = n - dw * 49;
    int hw  = rem / 7;
    int wl  = rem - hw * 7;
    int d  = wd * 2 + dw;
    int hh = wh * 7 + hw;
    int w  = ww * 7 + wl;
    return ((b * 16 + d) * 56 + hh) * 56 + w;
}

// ---------------------------------------------------------------------------
// LayerNorm: one warp per row of 512. gather=1: read x[w2o(row)]
// ---------------------------------------------------------------------------
__global__ void ln_kernel(const float* __restrict__ x, const float* __restrict__ g,
                          const float* __restrict__ b, float* __restrict__ out,
                          int gather)
{
    int row  = blockIdx.x * 8 + (threadIdx.x >> 5);
    int lane = threadIdx.x & 31;
    if (row >= TOKENS) return;
    int src = gather ? w2o(row) : row;
    const float* xr = x + (size_t)src * CDIM;

    float v[16], s = 0.f, ss = 0.f;
#pragma unroll
    for (int k = 0; k < 16; ++k) {
        float a = xr[lane + 32 * k];
        v[k] = a; s += a; ss += a * a;
    }
#pragma unroll
    for (int off = 16; off; off >>= 1) {
        s  += __shfl_xor_sync(0xffffffffu, s,  off);
        ss += __shfl_xor_sync(0xffffffffu, ss, off);
    }
    float mu   = s * (1.f / 512.f);
    float var  = ss * (1.f / 512.f) - mu * mu;
    float rstd = rsqrtf(var + 1e-5f);

    float* orow = out + (size_t)row * CDIM;
#pragma unroll
    for (int k = 0; k < 16; ++k) {
        int c = lane + 32 * k;
        orow[c] = (v[k] - mu) * rstd * g[c] + b[c];
    }
}

// ---------------------------------------------------------------------------
// BF16x2 GEMM: C[M,N] = A[M,K] @ B[K,N] (+bias, +gelu, +res/scatter)
// 128x128 block tile, BK=16, 256 threads, warp grid 2x4, warp tile 64x32,
// mma.sync.m16n8k16 bf16 with hi/lo split (3 mma: hh + hl + lh).
// smem: A[m][k] and B[n][k], bf16, row stride 24 elems (48B, ldmatrix-aligned,
// conflict-free row->bank map). Double buffered: exactly 48KB static shared.
// ---------------------------------------------------------------------------
#define GSTRIDE 24                       // bf16 elems per smem row (128 rows)
#define GAR     1536                     // u32 words per array (128*24/2)
#define GBUF    (4 * GAR)                // words per buffer (Ahi,Alo,Bhi,Blo)

// pack (x0, x1) -> bf16x2 (x0 in low half), and the bf16 residuals
__device__ __forceinline__ void split2(float x0, float x1, unsigned& hi, unsigned& lo) {
    unsigned h;
    asm("cvt.rn.bf16x2.f32 %0, %1, %2;" : "=r"(h) : "f"(x1), "f"(x0));
    float h0 = __uint_as_float(h << 16);
    float h1 = __uint_as_float(h & 0xffff0000u);
    float l0 = x0 - h0, l1 = x1 - h1;
    unsigned l;
    asm("cvt.rn.bf16x2.f32 %0, %1, %2;" : "=r"(l) : "f"(l1), "f"(l0));
    hi = h; lo = l;
}

__device__ __forceinline__ void ldsm4(unsigned r[4], unsigned addr) {
    asm volatile("ldmatrix.sync.aligned.m8n8.x4.shared.b16 {%0,%1,%2,%3}, [%4];"
                 : "=r"(r[0]), "=r"(r[1]), "=r"(r[2]), "=r"(r[3]) : "r"(addr));
}

__device__ __forceinline__ void mma16(float c[4], const unsigned a[4], const unsigned b[2]) {
    asm volatile(
        "mma.sync.aligned.m16n8k16.row.col.f32.bf16.bf16.f32 "
        "{%0,%1,%2,%3},{%4,%5,%6,%7},{%8,%9},{%0,%1,%2,%3};"
        : "+f"(c[0]), "+f"(c[1]), "+f"(c[2]), "+f"(c[3])
        : "r"(a[0]), "r"(a[1]), "r"(a[2]), "r"(a[3]), "r"(b[0]), "r"(b[1]));
}

__device__ __forceinline__ float gelu_tanh(float x) {
    float u = 0.7978845608028654f * (x + 0.044715f * x * x * x);
    return 0.5f * x * (1.f + tanhf(u));
}

// A: thread t loads 2 float4 (rows f>>2, k-quad f&3); B: 8 strided LDG.32
__device__ __forceinline__ void gemm_ldg(const float* __restrict__ A,
                                         const float* __restrict__ Bw,
                                         int K, int N, int bm, int bn, int kt, int t,
                                         float ra[8], float rb[8])
{
    const float* Ap = A + (size_t)bm * K + (size_t)kt * 16;
#pragma unroll
    for (int r = 0; r < 2; ++r) {
        int f = t + 256 * r;
        int row = f >> 2, q = f & 3;
        float4 v = *(const float4*)(Ap + (size_t)row * K + q * 4);
        ra[4*r+0] = v.x; ra[4*r+1] = v.y; ra[4*r+2] = v.z; ra[4*r+3] = v.w;
    }
    const float* Bp = Bw + (size_t)(kt * 16) * N + bn;
    int n  = t & 127;
    int kh = t >> 7;            // 0/1 -> k 0..7 / 8..15
#pragma unroll
    for (int i = 0; i < 8; ++i)
        rb[i] = Bp[(size_t)(kh * 8 + i) * N + n];
}

__device__ __forceinline__ void gemm_sts(unsigned* sAhi, unsigned* sAlo,
                                         unsigned* sBhi, unsigned* sBlo,
                                         int t, const float ra[8], const float rb[8])
{
    // A -> [m][k], 4 consecutive k per store pair
#pragma unroll
    for (int r = 0; r < 2; ++r) {
        int f = t + 256 * r;
        int row = f >> 2, q = f & 3;
        unsigned h0, l0, h1, l1;
        split2(ra[4*r+0], ra[4*r+1], h0, l0);
        split2(ra[4*r+2], ra[4*r+3], h1, l1);
        int idx = row * 12 + q * 2;                 // u32 index
        *(uint2*)&sAhi[idx] = make_uint2(h0, h1);
        *(uint2*)&sAlo[idx] = make_uint2(l0, l1);
    }
    // B -> [n][k], 8 consecutive k per thread
    int n  = t & 127;
    int kh = t >> 7;
    unsigned h[4], l[4];
    split2(rb[0], rb[1], h[0], l[0]);
    split2(rb[2], rb[3], h[1], l[1]);
    split2(rb[4], rb[5], h[2], l[2]);
    split2(rb[6], rb[7], h[3], l[3]);
    int idx = n * 12 + kh * 4;
    *(uint4*)&sBhi[idx] = make_uint4(h[0], h[1], h[2], h[3]);
    *(uint4*)&sBlo[idx] = make_uint4(l[0], l[1], l[2], l[3]);
}

// one k16 step of compute from a buffered tile (byte base addresses in smem space)
__device__ __forceinline__ void gemm_compute(unsigned aHiB, unsigned aLoB,
                                             unsigned bHiB, unsigned bLoB,
                                             int wm, int wn, int lane, float c[4][4][4])
{
    int mat  = lane >> 3;
    int rsub = lane & 7;
    // A: matrices (m0-7,k0-7),(m8-15,k0-7),(m0-7,k8-15),(m8-15,k8-15)
    int a_row = (mat & 1) * 8 + rsub;
    int a_kb  = (mat >> 1) * 16;             // byte offset of k-half
    // B: matrices (n0-7,k0-7),(n0-7,k8-15),(n8-15,k0-7),(n8-15,k8-15)
    int b_row = (mat >> 1) * 8 + rsub;
    int b_kb  = (mat & 1) * 16;

    unsigned Ahi[4][4], Alo[4][4], Bhi[2][4], Blo[2][4];
#pragma unroll
    for (int i = 0; i < 4; ++i) {
        unsigned off = (unsigned)((wm * 64 + i * 16 + a_row) * 48 + a_kb);
        ldsm4(Ahi[i], aHiB + off);
        ldsm4(Alo[i], aLoB + off);
    }
#pragma unroll
    for (int g = 0; g < 2; ++g) {
        unsigned off = (unsigned)((wn * 32 + g * 16 + b_row) * 48 + b_kb);
        ldsm4(Bhi[g], bHiB + off);
        ldsm4(Blo[g], bLoB + off);
    }
#pragma unroll
    for (int i = 0; i < 4; ++i)
#pragma unroll
        for (int j = 0; j < 4; ++j) {
            const unsigned* bh = &Bhi[j >> 1][(j & 1) * 2];
            const unsigned* bl = &Blo[j >> 1][(j & 1) * 2];
            mma16(c[i][j], Ahi[i], bh);
            mma16(c[i][j], Ahi[i], bl);
            mma16(c[i][j], Alo[i], bh);
        }
}

// EPI: 0 = +bias ; 1 = +bias,gelu ; 2 = +bias,+res, scatter rows via w2o (N==512)
template <int EPI>
__global__ void __launch_bounds__(256, 1)
gemm_bf16x2(const float* __restrict__ A, const float* __restrict__ Bw,
            const float* __restrict__ bias, const float* __restrict__ res,
            float* __restrict__ Cm, int M, int N, int K)
{
    __shared__ unsigned smem_u[2 * GBUF];          // exactly 48 KB

    int t = threadIdx.x;
    int warp = t >> 5, lane = t & 31;
    int wm = warp >> 2, wn = warp & 3;
    int bm = blockIdx.y * 128, bn = blockIdx.x * 128;

    unsigned sbase = (unsigned)__cvta_generic_to_shared(smem_u);

    float c[4][4][4];
#pragma unroll
    for (int i = 0; i < 4; ++i)
#pragma unroll
        for (int j = 0; j < 4; ++j)
#pragma unroll
            for (int k = 0; k < 4; ++k) c[i][j][k] = 0.f;

    float ra[8], rb[8];
    gemm_ldg(A, Bw, K, N, bm, bn, 0, t, ra, rb);
    gemm_sts(smem_u, smem_u + GAR, smem_u + 2 * GAR, smem_u + 3 * GAR, t, ra, rb);
    __syncthreads();

    int KT = K >> 4;
    for (int kt = 0; kt < KT; ++kt) {
        int cur = kt & 1;
        if (kt + 1 < KT) gemm_ldg(A, Bw, K, N, bm, bn, kt + 1, t, ra, rb);
        unsigned base = sbase + (unsigned)cur * (GBUF * 4);
        gemm_compute(base, base + GAR * 4, base + 2 * GAR * 4, base + 3 * GAR * 4,
                     wm, wn, lane, c);
        if (kt + 1 < KT) {
            unsigned* nb = smem_u + (cur ^ 1) * GBUF;
            gemm_sts(nb, nb + GAR, nb + 2 * GAR, nb + 3 * GAR, t, ra, rb);
        }
        __syncthreads();
    }

    // epilogue (C frag: rows r0,r0+8 ; cols col,col+1)
#pragma unroll
    for (int i = 0; i < 4; ++i) {
        int r0 = bm + wm * 64 + i * 16 + (lane >> 2);
        int rows[2] = { r0, r0 + 8 };
        int dst[2];
        if (EPI == 2) { dst[0] = w2o(rows[0]); dst[1] = w2o(rows[1]); }
#pragma unroll
        for (int j = 0; j < 4; ++j) {
            int col = bn + wn * 32 + j * 8 + ((lane & 3) << 1);
            float bv0 = bias[col], bv1 = bias[col + 1];
#pragma unroll
            for (int rr = 0; rr < 2; ++rr) {
                float v0 = c[i][j][rr * 2 + 0] + bv0;
                float v1 = c[i][j][rr * 2 + 1] + bv1;
                if (EPI == 1) { v0 = gelu_tanh(v0); v1 = gelu_tanh(v1); }
                if (EPI == 2) {
                    size_t ro = (size_t)rows[rr] * CDIM + col;
                    v0 += res[ro]; v1 += res[ro + 1];
                    size_t oo = (size_t)dst[rr] * CDIM + col;
                    Cm[oo] = v0; Cm[oo + 1] = v1;
                } else {
                    size_t oo = (size_t)rows[rr] * (size_t)N + col;
                    Cm[oo] = v0; Cm[oo + 1] = v1;
                }
            }
        }
    }
}

// ---------------------------------------------------------------------------
// Windowed attention: one CTA per (window, head). 128 threads.
// smem: Q[98][32], K[98][36] (pad), Vt[32][100] (transposed, pad), P[98][100]
// ---------------------------------------------------------------------------
#define SQ_OFF  0
#define SK_OFF  3136
#define SVT_OFF (3136 + 3528)
#define SP_OFF  (SVT_OFF + 3200)
#define ATTN_SMEM_BYTES ((SP_OFF + 9800) * 4)   // 78656 B

__global__ void __launch_bounds__(128)
attn_kernel(const float* __restrict__ qkv, float* __restrict__ o)
{
    extern __shared__ float sm[];
    float* sQ  = sm + SQ_OFF;
    float* sK  = sm + SK_OFF;
    float* sVt = sm + SVT_OFF;
    float* sP  = sm + SP_OFF;

    int win  = blockIdx.x >> 4;
    int head = blockIdx.x & 15;
    int t = threadIdx.x, warp = t >> 5, lane = t & 31;

    if (t < 64) sVt[(t >> 1) * 100 + 98 + (t & 1)] = 0.f;

    const float scale = 0.17677669529663687f;   // 1/sqrt(32)
    size_t base = (size_t)win * 98 * QKVDIM + (size_t)head * 32;
    for (int idx = t; idx < 98 * 32; idx += 128) {
        int n = idx >> 5, hd = idx & 31;
        const float* p = qkv + base + (size_t)n * QKVDIM + hd;
        sQ[n * 32 + hd]   = p[0] * scale;
        sK[n * 36 + hd]   = p[512];
        sVt[hd * 100 + n] = p[1024];
    }
    __syncthreads();

    for (int i = warp; i < 98; i += 4) {
        float4 q4[8];
        const float4* qrow = (const float4*)(sQ + i * 32);
#pragma unroll
        for (int cc = 0; cc < 8; ++cc) q4[cc] = qrow[cc];

        float sv[4];
        float mx = -1e30f;
#pragma unroll
        for (int jj = 0; jj < 4; ++jj) {
            int j = lane + jj * 32;
            float a = -1e30f;
            if (j < 98) {
                const float4* krow = (const float4*)(sK + j * 36);
                float acc = 0.f;
#pragma unroll
                for (int cc = 0; cc < 8; ++cc) {
                    float4 k4 = krow[cc];
                    acc += q4[cc].x * k4.x + q4[cc].y * k4.y
                         + q4[cc].z * k4.z + q4[cc].w * k4.w;
                }
                a = acc;
            }
            sv[jj] = a;
            mx = fmaxf(mx, a);
        }
#pragma unroll
        for (int off = 16; off; off >>= 1)
            mx = fmaxf(mx, __shfl_xor_sync(0xffffffffu, mx, off));
        float sum = 0.f;
#pragma unroll
        for (int jj = 0; jj < 4; ++jj) {
            int j = lane + jj * 32;
            float e = (j < 98) ? __expf(sv[jj] - mx) : 0.f;
            sv[jj] = e; sum += e;
        }
#pragma unroll
        for (int off = 16; off; off >>= 1)
            sum += __shfl_xor_sync(0xffffffffu, sum, off);
        float inv = 1.f / sum;
#pragma unroll
        for (int jj = 0; jj < 4; ++jj) {
            int j = lane + jj * 32;
            if (j < 98) sP[i * 100 + j] = sv[jj] * inv;
        }
        if (lane < 2) sP[i * 100 + 98 + lane] = 0.f;
    }
    __syncthreads();

    size_t obase = (size_t)win * 98 * CDIM + (size_t)head * 32 + lane;
    const float4* vrow = (const float4*)(sVt + lane * 100);
    for (int i = warp; i < 98; i += 4) {
        const float4* prow = (const float4*)(sP + i * 100);
        float acc = 0.f;
#pragma unroll
        for (int cc = 0; cc < 25; ++cc) {
            float4 p4 = prow[cc];
            float4 v4 = vrow[cc];
            acc += p4.x * v4.x + p4.y * v4.y + p4.z * v4.z + p4.w * v4.w;
        }
        o[obase + (size_t)i * CDIM] = acc;
    }
}

// ---------------------------------------------------------------------------
// launch
// ---------------------------------------------------------------------------
extern "C" void kernel_launch(void* const* d_in, const int* in_sizes, int n_in,
                              void* d_out, int out_size)
{
    (void)in_sizes; (void)n_in; (void)out_size;

    const float* x     = (const float*)d_in[0];
    const float* g1    = (const float*)d_in[1];
    const float* b1    = (const float*)d_in[2];
    const float* wqkv  = (const float*)d_in[3];
    const float* bqkv  = (const float*)d_in[4];
    const float* wproj = (const float*)d_in[5];
    const float* bproj = (const float*)d_in[6];
    const float* g2    = (const float*)d_in[7];
    const float* b2    = (const float*)d_in[8];
    const float* w1    = (const float*)d_in[9];
    const float* bm1   = (const float*)d_in[10];
    const float* w2    = (const float*)d_in[11];
    const float* bm2   = (const float*)d_in[12];
    float* out = (float*)d_out;

    float *h, *qkv, *o, *attn, *hidden;
    cudaGetSymbolAddress((void**)&h,      g_h);
    cudaGetSymbolAddress((void**)&qkv,    g_qkv);
    cudaGetSymbolAddress((void**)&o,      g_o);
    cudaGetSymbolAddress((void**)&attn,   g_attn);
    cudaGetSymbolAddress((void**)&hidden, g_hidden);

    cudaFuncSetAttribute((const void*)attn_kernel,
                         cudaFuncAttributeMaxDynamicSharedMemorySize, ATTN_SMEM_BYTES);

    const int LN_BLOCKS = TOKENS / 8;   // 12544, 8 warps/block

    // 1. window-partition gather + LN1 -> h (windowed)
    ln_kernel<<<LN_BLOCKS, 256>>>(x, g1, b1, h, 1);

    // 2. qkv = h @ wqkv + bqkv
    gemm_bf16x2<0><<<dim3(QKVDIM / 128, TOKENS / 128), 256>>>(
        h, wqkv, bqkv, nullptr, qkv, TOKENS, QKVDIM, CDIM);

    // 3. windowed attention -> o (windowed, head-merged)
    attn_kernel<<<NWINHEAD, 128, ATTN_SMEM_BYTES>>>(qkv, o);

    // 4. attn = o @ wproj + bproj (stays windowed)
    gemm_bf16x2<0><<<dim3(CDIM / 128, TOKENS / 128), 256>>>(
        o, wproj, bproj, nullptr, attn, TOKENS, CDIM, CDIM);

    // 5. LN2 -> h (reuse)
    ln_kernel<<<LN_BLOCKS, 256>>>(attn, g2, b2, h, 0);

    // 6. hidden = gelu(h @ w1 + bm1)
    gemm_bf16x2<1><<<dim3(MLPDIM / 128, TOKENS / 128), 256>>>(
        h, w1, bm1, nullptr, hidden, TOKENS, MLPDIM, CDIM);

    // 7. out[w2o(m)] = attn[m] + hidden[m] @ w2 + bm2  (window reverse fused)
    gemm_bf16x2<2><<<dim3(CDIM / 128, TOKENS / 128), 256>>>(
        hidden, w2, bm2, attn, out, TOKENS, CDIM, MLPDIM);
}

// round 5
// speedup vs baseline: 2.0104x; 1.2150x over previous
#include <cuda_runtime.h>
#include <cuda_bf16.h>
#include <cstdint>

// ---------------------------------------------------------------------------
// Problem constants
// ---------------------------------------------------------------------------
#define TOKENS   100352          // B * D*H*W = 2*16*56*56 = 1024 windows * 98
#define CDIM     512
#define QKVDIM   1536
#define MLPDIM   2048
#define NWINHEAD 16384           // 1024 windows * 16 heads

typedef unsigned short u16;

// ---------------------------------------------------------------------------
// Scratch (static device arrays; no runtime allocation allowed)
// ---------------------------------------------------------------------------
__device__ u16   g_hh [(size_t)TOKENS * CDIM];     // LN out hi  (bf16 bits)
__device__ u16   g_hl [(size_t)TOKENS * CDIM];     // LN out lo
__device__ float g_qkv[(size_t)TOKENS * QKVDIM];   // qkv fp32 (attention wants accuracy)
__device__ u16   g_oh [(size_t)TOKENS * CDIM];     // attention out hi
__device__ u16   g_ol [(size_t)TOKENS * CDIM];     // attention out lo
__device__ float g_attn[(size_t)TOKENS * CDIM];    // proj out fp32 ("xr", residual+LN2 src)
__device__ u16   g_mh [(size_t)TOKENS * MLPDIM];   // gelu(mlp1) hi
__device__ u16   g_ml [(size_t)TOKENS * MLPDIM];   // gelu(mlp1) lo
// transposed weights, [N][K] bf16 hi/lo
__device__ u16   g_wqkvh[QKVDIM * CDIM], g_wqkvl[QKVDIM * CDIM];
__device__ u16   g_wprh [CDIM * CDIM],   g_wprl [CDIM * CDIM];
__device__ u16   g_w1h  [MLPDIM * CDIM], g_w1l  [MLPDIM * CDIM];
__device__ u16   g_w2h  [CDIM * MLPDIM], g_w2l  [CDIM * MLPDIM];

// ---------------------------------------------------------------------------
// windowed token index -> original token index
// ---------------------------------------------------------------------------
__device__ __forceinline__ int w2o(int m) {
    int win = m / 98;
    int n   = m - win * 98;
    int b   = win >> 9;
    int r   = win & 511;
    int wd  = r >> 6;
    int wh  = (r >> 3) & 7;
    int ww  = r & 7;
    int dw  = n / 49;
    int rem = n - dw * 49;
    int hw  = rem / 7;
    int wl  = rem - hw * 7;
    int d  = wd * 2 + dw;
    int hh = wh * 7 + hw;
    int w  = ww * 7 + wl;
    return ((b * 16 + d) * 56 + hh) * 56 + w;
}

// bf16 hi/lo split of a single fp32
__device__ __forceinline__ void split1(float x, u16& hi, u16& lo) {
    __nv_bfloat16 h = __float2bfloat16(x);
    float r = x - __bfloat162float(h);
    __nv_bfloat16 l = __float2bfloat16(r);
    hi = *reinterpret_cast<u16*>(&h);
    lo = *reinterpret_cast<u16*>(&l);
}

// pack (x0, x1) -> bf16x2 hi and lo words (x0 in low half)
__device__ __forceinline__ void split2(float x0, float x1, unsigned& hi, unsigned& lo) {
    unsigned h;
    asm("cvt.rn.bf16x2.f32 %0, %1, %2;" : "=r"(h) : "f"(x1), "f"(x0));
    float h0 = __uint_as_float(h << 16);
    float h1 = __uint_as_float(h & 0xffff0000u);
    float l0 = x0 - h0, l1 = x1 - h1;
    unsigned l;
    asm("cvt.rn.bf16x2.f32 %0, %1, %2;" : "=r"(l) : "f"(l1), "f"(l0));
    hi = h; lo = l;
}

// ---------------------------------------------------------------------------
// Weight convert + transpose: w[K][N] fp32 -> wt_hi/lo [N][K] bf16
// ---------------------------------------------------------------------------
__global__ void wconv_kernel(const float* __restrict__ w, u16* __restrict__ th,
                             u16* __restrict__ tl, int K, int N)
{
    __shared__ float tile[32][33];
    int n0 = blockIdx.x * 32, k0 = blockIdx.y * 32;
    int tx = threadIdx.x, ty = threadIdx.y;     // block (32, 8)
#pragma unroll
    for (int r = 0; r < 4; ++r)
        tile[ty + 8 * r][tx] = w[(size_t)(k0 + ty + 8 * r) * N + n0 + tx];
    __syncthreads();
#pragma unroll
    for (int r = 0; r < 4; ++r) {
        int n = n0 + ty + 8 * r, k = k0 + tx;
        float v = tile[tx][ty + 8 * r];
        u16 h, l; split1(v, h, l);
        th[(size_t)n * K + k] = h;
        tl[(size_t)n * K + k] = l;
    }
}

// ---------------------------------------------------------------------------
// LayerNorm -> bf16 hi/lo. gather=1: read x[w2o(row)]
// ---------------------------------------------------------------------------
__global__ void ln_kernel(const float* __restrict__ x, const float* __restrict__ g,
                          const float* __restrict__ b, u16* __restrict__ oh,
                          u16* __restrict__ ol, int gather)
{
    int row  = blockIdx.x * 8 + (threadIdx.x >> 5);
    int lane = threadIdx.x & 31;
    if (row >= TOKENS) return;
    int src = gather ? w2o(row) : row;
    const float* xr = x + (size_t)src * CDIM;

    float v[16], s = 0.f, ss = 0.f;
#pragma unroll
    for (int k = 0; k < 16; ++k) {
        float a = xr[lane + 32 * k];
        v[k] = a; s += a; ss += a * a;
    }
#pragma unroll
    for (int off = 16; off; off >>= 1) {
        s  += __shfl_xor_sync(0xffffffffu, s,  off);
        ss += __shfl_xor_sync(0xffffffffu, ss, off);
    }
    float mu   = s * (1.f / 512.f);
    float var  = ss * (1.f / 512.f) - mu * mu;
    float rstd = rsqrtf(var + 1e-5f);

    size_t ro = (size_t)row * CDIM;
#pragma unroll
    for (int k = 0; k < 16; ++k) {
        int c = lane + 32 * k;
        float y = (v[k] - mu) * rstd * g[c] + b[c];
        u16 h, l; split1(y, h, l);
        oh[ro + c] = h; ol[ro + c] = l;
    }
}

// ---------------------------------------------------------------------------
// BF16x2 GEMM v2: inputs pre-split bf16 hi/lo in gmem.
//   A: [M][K] bf16 (hi,lo)    B: [N][K] bf16 (hi,lo)
// 128x128x16 tiles, 256 thr, warp 2x4, warp tile 64x32, 3-stage cp.async.
// smem per stage: Ahi|Alo|Bhi|Blo, each 128 rows x 32B, XOR-swizzled:
//   addr(row, khalf) = row*32 + ((khalf ^ ((row>>2)&1)) << 4)   (conflict-free)
// MMA: m16n8k16 bf16, 3 terms (AhBh + AhBl + AlBh).
// ---------------------------------------------------------------------------
#define STG_BYTES 16384          // 4 arrays * 4KB
#define OFF_AL    4096
#define OFF_BH    8192
#define OFF_BL    12288

__device__ __forceinline__ void ldsm4(unsigned r[4], unsigned addr) {
    asm volatile("ldmatrix.sync.aligned.m8n8.x4.shared.b16 {%0,%1,%2,%3}, [%4];"
                 : "=r"(r[0]), "=r"(r[1]), "=r"(r[2]), "=r"(r[3]) : "r"(addr));
}

__device__ __forceinline__ void mma16(float c[4], const unsigned a[4], const unsigned b[2]) {
    asm volatile(
        "mma.sync.aligned.m16n8k16.row.col.f32.bf16.bf16.f32 "
        "{%0,%1,%2,%3},{%4,%5,%6,%7},{%8,%9},{%0,%1,%2,%3};"
        : "+f"(c[0]), "+f"(c[1]), "+f"(c[2]), "+f"(c[3])
        : "r"(a[0]), "r"(a[1]), "r"(a[2]), "r"(a[3]), "r"(b[0]), "r"(b[1]));
}

__device__ __forceinline__ float gelu_tanh(float x) {
    float u = 0.7978845608028654f * (x + 0.044715f * x * x * x);
    return 0.5f * x * (1.f + tanhf(u));
}

__device__ __forceinline__ void cpasync16(unsigned dst, const void* src) {
    asm volatile("cp.async.cg.shared.global [%0], [%1], 16;" :: "r"(dst), "l"(src));
}

__device__ __forceinline__ unsigned swz(int row, int khalf) {
    return (unsigned)(row * 32 + (((khalf) ^ ((row >> 2) & 1)) << 4));
}

// one stage of loads: thread t -> (row = t>>1, khalf = t&1), one 16B chunk per array
__device__ __forceinline__ void load_stage(unsigned sb,
                                           const u16* __restrict__ Ah, const u16* __restrict__ Al,
                                           const u16* __restrict__ Bh, const u16* __restrict__ Bl,
                                           int K, int bm, int bn, int kt, int t)
{
    int row = t >> 1, khalf = t & 1;
    unsigned so = swz(row, khalf);
    size_t ga = (size_t)(bm + row) * K + kt * 16 + khalf * 8;
    size_t gb = (size_t)(bn + row) * K + kt * 16 + khalf * 8;
    cpasync16(sb + so,          Ah + ga);
    cpasync16(sb + OFF_AL + so, Al + ga);
    cpasync16(sb + OFF_BH + so, Bh + gb);
    cpasync16(sb + OFF_BL + so, Bl + gb);
}

__device__ __forceinline__ void compute_k16(unsigned base, int wm, int wn, int lane,
                                            float c[4][4][4])
{
    int mat  = lane >> 3;
    int rsub = lane & 7;
    int aRow = (mat & 1) * 8 + rsub;  int aKh = mat >> 1;
    int bRow = (mat >> 1) * 8 + rsub; int bKh = mat & 1;

    unsigned Ahi[4][4], Bhi[2][4], Blo[2][4];
#pragma unroll
    for (int i = 0; i < 4; ++i)
        ldsm4(Ahi[i], base + swz(wm * 64 + i * 16 + aRow, aKh));
#pragma unroll
    for (int g = 0; g < 2; ++g) {
        unsigned so = swz(wn * 32 + g * 16 + bRow, bKh);
        ldsm4(Bhi[g], base + OFF_BH + so);
        ldsm4(Blo[g], base + OFF_BL + so);
    }
    // hh + hl
#pragma unroll
    for (int i = 0; i < 4; ++i)
#pragma unroll
        for (int j = 0; j < 4; ++j) {
            mma16(c[i][j], Ahi[i], &Bhi[j >> 1][(j & 1) * 2]);
            mma16(c[i][j], Ahi[i], &Blo[j >> 1][(j & 1) * 2]);
        }
    // lh
    unsigned Alo[4][4];
#pragma unroll
    for (int i = 0; i < 4; ++i)
        ldsm4(Alo[i], base + OFF_AL + swz(wm * 64 + i * 16 + aRow, aKh));
#pragma unroll
    for (int i = 0; i < 4; ++i)
#pragma unroll
        for (int j = 0; j < 4; ++j)
            mma16(c[i][j], Alo[i], &Bhi[j >> 1][(j & 1) * 2]);
}

// EPI: 0 = +bias -> fp32 ; 1 = +bias,gelu -> bf16 hi/lo ; 2 = +bias+res, w2o scatter -> fp32
template <int EPI>
__global__ void __launch_bounds__(256, 2)
gemm_bf16(const u16* __restrict__ Ah, const u16* __restrict__ Al,
          const u16* __restrict__ Bh, const u16* __restrict__ Bl,
          const float* __restrict__ bias, const float* __restrict__ res,
          float* __restrict__ Cf, u16* __restrict__ Ch, u16* __restrict__ Cl,
          int N, int K)
{
    __shared__ char sm_raw[3 * STG_BYTES];
    unsigned sb = (unsigned)__cvta_generic_to_shared(sm_raw);

    int t = threadIdx.x;
    int warp = t >> 5, lane = t & 31;
    int wm = warp >> 2, wn = warp & 3;
    int bm = blockIdx.y * 128, bn = blockIdx.x * 128;

    float c[4][4][4];
#pragma unroll
    for (int i = 0; i < 4; ++i)
#pragma unroll
        for (int j = 0; j < 4; ++j)
#pragma unroll
            for (int k = 0; k < 4; ++k) c[i][j][k] = 0.f;

    int KT = K >> 4;
    load_stage(sb, Ah, Al, Bh, Bl, K, bm, bn, 0, t);
    asm volatile("cp.async.commit_group;");
    load_stage(sb + STG_BYTES, Ah, Al, Bh, Bl, K, bm, bn, 1, t);
    asm volatile("cp.async.commit_group;");

    for (int kt = 0; kt < KT; ++kt) {
        if (kt < KT - 1) asm volatile("cp.async.wait_group 1;");
        else             asm volatile("cp.async.wait_group 0;");
        __syncthreads();
        if (kt + 2 < KT) {
            load_stage(sb + (unsigned)((kt + 2) % 3) * STG_BYTES,
                       Ah, Al, Bh, Bl, K, bm, bn, kt + 2, t);
            asm volatile("cp.async.commit_group;");
        }
        compute_k16(sb + (unsigned)(kt % 3) * STG_BYTES, wm, wn, lane, c);
    }

    // epilogue (C frag: rows r0,r0+8 ; cols col,col+1)
#pragma unroll
    for (int i = 0; i < 4; ++i) {
        int r0 = bm + wm * 64 + i * 16 + (lane >> 2);
        int rows[2] = { r0, r0 + 8 };
        int dst[2];
        if (EPI == 2) { dst[0] = w2o(rows[0]); dst[1] = w2o(rows[1]); }
#pragma unroll
        for (int j = 0; j < 4; ++j) {
            int col = bn + wn * 32 + j * 8 + ((lane & 3) << 1);
            float bv0 = bias[col], bv1 = bias[col + 1];
#pragma unroll
            for (int rr = 0; rr < 2; ++rr) {
                float v0 = c[i][j][rr * 2 + 0] + bv0;
                float v1 = c[i][j][rr * 2 + 1] + bv1;
                if (EPI == 0) {
                    size_t oo = (size_t)rows[rr] * (size_t)N + col;
                    Cf[oo] = v0; Cf[oo + 1] = v1;
                } else if (EPI == 1) {
                    v0 = gelu_tanh(v0); v1 = gelu_tanh(v1);
                    unsigned h, l; split2(v0, v1, h, l);
                    size_t oo = (size_t)rows[rr] * (size_t)N + col;
                    *reinterpret_cast<unsigned*>(Ch + oo) = h;
                    *reinterpret_cast<unsigned*>(Cl + oo) = l;
                } else {
                    size_t ro = (size_t)rows[rr] * CDIM + col;
                    v0 += res[ro]; v1 += res[ro + 1];
                    size_t oo = (size_t)dst[rr] * CDIM + col;
                    Cf[oo] = v0; Cf[oo + 1] = v1;
                }
            }
        }
    }
}

// ---------------------------------------------------------------------------
// Windowed attention: one CTA per (window, head). 128 threads. fp32 SIMT.
// smem: Q[98][32], K[98][36] (pad), Vt[32][100] (transposed, pad), P[98][100]
// Output written as bf16 hi/lo (proj GEMM input).
// ---------------------------------------------------------------------------
#define SQ_OFF  0
#define SK_OFF  3136
#define SVT_OFF (3136 + 3528)
#define SP_OFF  (SVT_OFF + 3200)
#define ATTN_SMEM_BYTES ((SP_OFF + 9800) * 4)   // 78656 B

__global__ void __launch_bounds__(128)
attn_kernel(const float* __restrict__ qkv, u16* __restrict__ oh, u16* __restrict__ ol)
{
    extern __shared__ float sm[];
    float* sQ  = sm + SQ_OFF;
    float* sK  = sm + SK_OFF;
    float* sVt = sm + SVT_OFF;
    float* sP  = sm + SP_OFF;

    int win  = blockIdx.x >> 4;
    int head = blockIdx.x & 15;
    int t = threadIdx.x, warp = t >> 5, lane = t & 31;

    if (t < 64) sVt[(t >> 1) * 100 + 98 + (t & 1)] = 0.f;

    const float scale = 0.17677669529663687f;   // 1/sqrt(32)
    size_t base = (size_t)win * 98 * QKVDIM + (size_t)head * 32;
    for (int idx = t; idx < 98 * 32; idx += 128) {
        int n = idx >> 5, hd = idx & 31;
        const float* p = qkv + base + (size_t)n * QKVDIM + hd;
        sQ[n * 32 + hd]   = p[0] * scale;
        sK[n * 36 + hd]   = p[512];
        sVt[hd * 100 + n] = p[1024];
    }
    __syncthreads();

    for (int i = warp; i < 98; i += 4) {
        float4 q4[8];
        const float4* qrow = (const float4*)(sQ + i * 32);
#pragma unroll
        for (int cc = 0; cc < 8; ++cc) q4[cc] = qrow[cc];

        float sv[4];
        float mx = -1e30f;
#pragma unroll
        for (int jj = 0; jj < 4; ++jj) {
            int j = lane + jj * 32;
            float a = -1e30f;
            if (j < 98) {
                const float4* krow = (const float4*)(sK + j * 36);
                float acc = 0.f;
#pragma unroll
                for (int cc = 0; cc < 8; ++cc) {
                    float4 k4 = krow[cc];
                    acc += q4[cc].x * k4.x + q4[cc].y * k4.y
                         + q4[cc].z * k4.z + q4[cc].w * k4.w;
                }
                a = acc;
            }
            sv[jj] = a;
            mx = fmaxf(mx, a);
        }
#pragma unroll
        for (int off = 16; off; off >>= 1)
            mx = fmaxf(mx, __shfl_xor_sync(0xffffffffu, mx, off));
        float sum = 0.f;
#pragma unroll
        for (int jj = 0; jj < 4; ++jj) {
            int j = lane + jj * 32;
            float e = (j < 98) ? __expf(sv[jj] - mx) : 0.f;
            sv[jj] = e; sum += e;
        }
#pragma unroll
        for (int off = 16; off; off >>= 1)
            sum += __shfl_xor_sync(0xffffffffu, sum, off);
        float inv = 1.f / sum;
#pragma unroll
        for (int jj = 0; jj < 4; ++jj) {
            int j = lane + jj * 32;
            if (j < 98) sP[i * 100 + j] = sv[jj] * inv;
        }
        if (lane < 2) sP[i * 100 + 98 + lane] = 0.f;
    }
    __syncthreads();

    size_t obase = (size_t)win * 98 * CDIM + (size_t)head * 32 + lane;
    const float4* vrow = (const float4*)(sVt + lane * 100);
    for (int i = warp; i < 98; i += 4) {
        const float4* prow = (const float4*)(sP + i * 100);
        float acc = 0.f;
#pragma unroll
        for (int cc = 0; cc < 25; ++cc) {
            float4 p4 = prow[cc];
            float4 v4 = vrow[cc];
            acc += p4.x * v4.x + p4.y * v4.y + p4.z * v4.z + p4.w * v4.w;
        }
        u16 h, l; split1(acc, h, l);
        oh[obase + (size_t)i * CDIM] = h;
        ol[obase + (size_t)i * CDIM] = l;
    }
}

// ---------------------------------------------------------------------------
// launch
// ---------------------------------------------------------------------------
extern "C" void kernel_launch(void* const* d_in, const int* in_sizes, int n_in,
                              void* d_out, int out_size)
{
    (void)in_sizes; (void)n_in; (void)out_size;

    const float* x     = (const float*)d_in[0];
    const float* g1    = (const float*)d_in[1];
    const float* b1    = (const float*)d_in[2];
    const float* wqkv  = (const float*)d_in[3];
    const float* bqkv  = (const float*)d_in[4];
    const float* wproj = (const float*)d_in[5];
    const float* bproj = (const float*)d_in[6];
    const float* g2    = (const float*)d_in[7];
    const float* b2    = (const float*)d_in[8];
    const float* w1    = (const float*)d_in[9];
    const float* bm1   = (const float*)d_in[10];
    const float* w2    = (const float*)d_in[11];
    const float* bm2   = (const float*)d_in[12];
    float* out = (float*)d_out;

    u16 *hh, *hl, *oh, *ol, *mh, *ml;
    u16 *wqh, *wql, *wph, *wpl, *w1h, *w1l, *w2h, *w2l;
    float *qkv, *attn;
    cudaGetSymbolAddress((void**)&hh,  g_hh);   cudaGetSymbolAddress((void**)&hl,  g_hl);
    cudaGetSymbolAddress((void**)&qkv, g_qkv);
    cudaGetSymbolAddress((void**)&oh,  g_oh);   cudaGetSymbolAddress((void**)&ol,  g_ol);
    cudaGetSymbolAddress((void**)&attn,g_attn);
    cudaGetSymbolAddress((void**)&mh,  g_mh);   cudaGetSymbolAddress((void**)&ml,  g_ml);
    cudaGetSymbolAddress((void**)&wqh, g_wqkvh); cudaGetSymbolAddress((void**)&wql, g_wqkvl);
    cudaGetSymbolAddress((void**)&wph, g_wprh);  cudaGetSymbolAddress((void**)&wpl, g_wprl);
    cudaGetSymbolAddress((void**)&w1h, g_w1h);   cudaGetSymbolAddress((void**)&w1l, g_w1l);
    cudaGetSymbolAddress((void**)&w2h, g_w2h);   cudaGetSymbolAddress((void**)&w2l, g_w2l);

    cudaFuncSetAttribute((const void*)attn_kernel,
                         cudaFuncAttributeMaxDynamicSharedMemorySize, ATTN_SMEM_BYTES);

    dim3 wblk(32, 8);
    // weight convert+transpose (w[K][N] -> [N][K] bf16 hi/lo)
    wconv_kernel<<<dim3(QKVDIM / 32, CDIM / 32), wblk>>>(wqkv, wqh, wql, CDIM, QKVDIM);
    wconv_kernel<<<dim3(CDIM / 32, CDIM / 32),   wblk>>>(wproj, wph, wpl, CDIM, CDIM);
    wconv_kernel<<<dim3(MLPDIM / 32, CDIM / 32), wblk>>>(w1, w1h, w1l, CDIM, MLPDIM);
    wconv_kernel<<<dim3(CDIM / 32, MLPDIM / 32), wblk>>>(w2, w2h, w2l, MLPDIM, CDIM);

    const int LN_BLOCKS = TOKENS / 8;   // 12544

    // 1. window-partition gather + LN1 -> hh/hl (bf16, windowed)
    ln_kernel<<<LN_BLOCKS, 256>>>(x, g1, b1, hh, hl, 1);

    // 2. qkv = h @ wqkv + bqkv  (fp32 out)
    gemm_bf16<0><<<dim3(QKVDIM / 128, TOKENS / 128), 256>>>(
        hh, hl, wqh, wql, bqkv, nullptr, qkv, nullptr, nullptr, QKVDIM, CDIM);

    // 3. windowed attention -> oh/ol (bf16, windowed, head-merged)
    attn_kernel<<<NWINHEAD, 128, ATTN_SMEM_BYTES>>>(qkv, oh, ol);

    // 4. attn = o @ wproj + bproj  (fp32, stays windowed)
    gemm_bf16<0><<<dim3(CDIM / 128, TOKENS / 128), 256>>>(
        oh, ol, wph, wpl, bproj, nullptr, attn, nullptr, nullptr, CDIM, CDIM);

    // 5. LN2 -> hh/hl (reuse)
    ln_kernel<<<LN_BLOCKS, 256>>>(attn, g2, b2, hh, hl, 0);

    // 6. mh/ml = gelu(h @ w1 + bm1)  (bf16 out)
    gemm_bf16<1><<<dim3(MLPDIM / 128, TOKENS / 128), 256>>>(
        hh, hl, w1h, w1l, bm1, nullptr, nullptr, mh, ml, MLPDIM, CDIM);

    // 7. out[w2o(m)] = attn[m] + hidden[m] @ w2 + bm2  (window reverse fused)
    gemm_bf16<2><<<dim3(CDIM / 128, TOKENS / 128), 256>>>(
        mh, ml, w2h, w2l, bm2, attn, out, nullptr, nullptr, CDIM, MLPDIM);
}

// round 8
// speedup vs baseline: 2.0753x; 1.0323x over previous
#include <cuda_runtime.h>
#include <cuda_bf16.h>
#include <cstdint>

// ---------------------------------------------------------------------------
// Problem constants
// ---------------------------------------------------------------------------
#define TOKENS   100352          // 1024 windows * 98
#define CDIM     512
#define QKVDIM   1536
#define MLPDIM   2048
#define NWINHEAD 16384

typedef unsigned short u16;

// ---------------------------------------------------------------------------
// Scratch (static device arrays)
// ---------------------------------------------------------------------------
__device__ __align__(16) u16   g_hh [(size_t)TOKENS * CDIM];
__device__ __align__(16) u16   g_hl [(size_t)TOKENS * CDIM];
__device__ __align__(16) float g_qkv[(size_t)TOKENS * QKVDIM];
__device__ __align__(16) u16   g_oh [(size_t)TOKENS * CDIM];
__device__ __align__(16) u16   g_ol [(size_t)TOKENS * CDIM];
__device__ __align__(16) float g_attn[(size_t)TOKENS * CDIM];
__device__ __align__(16) u16   g_mh [(size_t)TOKENS * MLPDIM];
__device__ __align__(16) u16   g_ml [(size_t)TOKENS * MLPDIM];
__device__ __align__(16) u16   g_wqkvh[QKVDIM * CDIM], g_wqkvl[QKVDIM * CDIM];
__device__ __align__(16) u16   g_wprh [CDIM * CDIM],   g_wprl [CDIM * CDIM];
__device__ __align__(16) u16   g_w1h  [MLPDIM * CDIM], g_w1l  [MLPDIM * CDIM];
__device__ __align__(16) u16   g_w2h  [CDIM * MLPDIM], g_w2l  [CDIM * MLPDIM];

// ---------------------------------------------------------------------------
// helpers
// ---------------------------------------------------------------------------
__device__ __forceinline__ int w2o(int m) {
    int win = m / 98;
    int n   = m - win * 98;
    int b   = win >> 9;
    int r   = win & 511;
    int wd  = r >> 6;
    int wh  = (r >> 3) & 7;
    int ww  = r & 7;
    int dw  = n / 49;
    int rem = n - dw * 49;
    int hw  = rem / 7;
    int wl  = rem - hw * 7;
    return (((b * 16 + wd * 2 + dw) * 56) + wh * 7 + hw) * 56 + ww * 7 + wl;
}

__device__ __forceinline__ void split1(float x, u16& hi, u16& lo) {
    __nv_bfloat16 h = __float2bfloat16(x);
    float r = x - __bfloat162float(h);
    __nv_bfloat16 l = __float2bfloat16(r);
    hi = *reinterpret_cast<u16*>(&h);
    lo = *reinterpret_cast<u16*>(&l);
}

__device__ __forceinline__ void split2(float x0, float x1, unsigned& hi, unsigned& lo) {
    unsigned h;
    asm("cvt.rn.bf16x2.f32 %0, %1, %2;" : "=r"(h) : "f"(x1), "f"(x0));
    float h0 = __uint_as_float(h << 16);
    float h1 = __uint_as_float(h & 0xffff0000u);
    unsigned l;
    asm("cvt.rn.bf16x2.f32 %0, %1, %2;" : "=r"(l) : "f"(x1 - h1), "f"(x0 - h0));
    hi = h; lo = l;
}

__device__ __forceinline__ float gelu_tanh(float x) {
    float u = 0.7978845608028654f * (x + 0.044715f * x * x * x);
    return 0.5f * x * (1.f + tanhf(u));
}

__device__ __forceinline__ void cpasync16(unsigned dst, const void* src) {
    asm volatile("cp.async.cg.shared.global [%0], [%1], 16;" :: "r"(dst), "l"(src));
}

__device__ __forceinline__ void ldsm4(unsigned r[4], unsigned addr) {
    asm volatile("ldmatrix.sync.aligned.m8n8.x4.shared.b16 {%0,%1,%2,%3}, [%4];"
                 : "=r"(r[0]), "=r"(r[1]), "=r"(r[2]), "=r"(r[3]) : "r"(addr));
}

__device__ __forceinline__ void mma16(float c[4], const unsigned a[4], const unsigned b[2]) {
    asm volatile(
        "mma.sync.aligned.m16n8k16.row.col.f32.bf16.bf16.f32 "
        "{%0,%1,%2,%3},{%4,%5,%6,%7},{%8,%9},{%0,%1,%2,%3};"
        : "+f"(c[0]), "+f"(c[1]), "+f"(c[2]), "+f"(c[3])
        : "r"(a[0]), "r"(a[1]), "r"(a[2]), "r"(a[3]), "r"(b[0]), "r"(b[1]));
}

// ---------------------------------------------------------------------------
// Weight convert + transpose: w[K][N] fp32 -> [N][K] bf16 hi/lo
// ---------------------------------------------------------------------------
__global__ void wconv_kernel(const float* __restrict__ w, u16* __restrict__ th,
                             u16* __restrict__ tl, int K, int N)
{
    __shared__ float tile[32][33];
    int n0 = blockIdx.x * 32, k0 = blockIdx.y * 32;
    int tx = threadIdx.x, ty = threadIdx.y;
#pragma unroll
    for (int r = 0; r < 4; ++r)
        tile[ty + 8 * r][tx] = w[(size_t)(k0 + ty + 8 * r) * N + n0 + tx];
    __syncthreads();
#pragma unroll
    for (int r = 0; r < 4; ++r) {
        int n = n0 + ty + 8 * r, k = k0 + tx;
        u16 h, l; split1(tile[tx][ty + 8 * r], h, l);
        th[(size_t)n * K + k] = h;
        tl[(size_t)n * K + k] = l;
    }
}

// ---------------------------------------------------------------------------
// LayerNorm -> bf16 hi/lo
// ---------------------------------------------------------------------------
__global__ void ln_kernel(const float* __restrict__ x, const float* __restrict__ g,
                          const float* __restrict__ b, u16* __restrict__ oh,
                          u16* __restrict__ ol, int gather)
{
    int row  = blockIdx.x * 8 + (threadIdx.x >> 5);
    int lane = threadIdx.x & 31;
    if (row >= TOKENS) return;
    int src = gather ? w2o(row) : row;
    const float* xr = x + (size_t)src * CDIM;

    float v[16], s = 0.f, ss = 0.f;
#pragma unroll
    for (int k = 0; k < 16; ++k) {
        float a = xr[lane + 32 * k];
        v[k] = a; s += a; ss += a * a;
    }
#pragma unroll
    for (int off = 16; off; off >>= 1) {
        s  += __shfl_xor_sync(0xffffffffu, s,  off);
        ss += __shfl_xor_sync(0xffffffffu, ss, off);
    }
    float mu   = s * (1.f / 512.f);
    float rstd = rsqrtf(ss * (1.f / 512.f) - mu * mu + 1e-5f);

    size_t ro = (size_t)row * CDIM;
#pragma unroll
    for (int k = 0; k < 16; ++k) {
        int c = lane + 32 * k;
        u16 h, l; split1((v[k] - mu) * rstd * g[c] + b[c], h, l);
        oh[ro + c] = h; ol[ro + c] = l;
    }
}

// ---------------------------------------------------------------------------
// BF16x2 GEMM v3 (legacy mma.sync path; sm_100 target has no tcgen05):
//   A: [M][K] bf16 (hi,lo)    B: [N][K] bf16 (hi,lo)
// 128x128 tile, BK=32, 3-stage cp.async ring, 256 thr, warps 2x4, wt 64x32.
// Stage (32KB): Ahi[128][32] | Alo | Bhi[128][32] | Blo, rows 64B.
// Swizzle: 16B chunk index c -> c ^ ((row>>1)&3)  (store & ldmatrix conflict-free)
// MMA: m16n8k16 bf16, 3 terms (AhBh + AhBl + AlBh).
// ---------------------------------------------------------------------------
#define STG32    32768
#define OFF_ALO  8192
#define OFF_BHI  16384
#define OFF_BLO  24576
#define GEMM_DSM (3 * STG32)     // 96KB dynamic

__device__ __forceinline__ unsigned swz64(int row, int c) {
    return (unsigned)(row * 64 + ((c ^ ((row >> 1) & 3)) << 4));
}

// thread t: 2 chunks per array; chunk ch -> row = ch>>2, c = ch&3 (8B u16 = 16B)
__device__ __forceinline__ void load_stage(unsigned sb,
    const u16* __restrict__ Ah, const u16* __restrict__ Al,
    const u16* __restrict__ Bh, const u16* __restrict__ Bl,
    int K, int bm, int bn, int kt, int t)
{
#pragma unroll
    for (int i = 0; i < 2; ++i) {
        int ch = t * 2 + i;
        int row = ch >> 2, c = ch & 3;
        unsigned so = swz64(row, c);
        size_t ga = (size_t)(bm + row) * K + kt * 32 + c * 8;
        size_t gb = (size_t)(bn + row) * K + kt * 32 + c * 8;
        cpasync16(sb + so,           Ah + ga);
        cpasync16(sb + OFF_ALO + so, Al + ga);
        cpasync16(sb + OFF_BHI + so, Bh + gb);
        cpasync16(sb + OFF_BLO + so, Bl + gb);
    }
}

// one k16 half (kk = 0/1) from a stage
__device__ __forceinline__ void compute_k16(unsigned base, int kk,
                                            int wm, int wn, int lane, float c[4][4][4])
{
    int mat  = lane >> 3;
    int rsub = lane & 7;
    int aRow = (mat & 1) * 8 + rsub;  int aCh = kk * 2 + (mat >> 1);
    int bRow = (mat >> 1) * 8 + rsub; int bCh = kk * 2 + (mat & 1);

    unsigned Ahi[4][4], Bhi[2][4], Blo[2][4];
#pragma unroll
    for (int i = 0; i < 4; ++i)
        ldsm4(Ahi[i], base + swz64(wm * 64 + i * 16 + aRow, aCh));
#pragma unroll
    for (int g = 0; g < 2; ++g) {
        int r = wn * 32 + g * 16 + bRow;
        ldsm4(Bhi[g], base + OFF_BHI + swz64(r, bCh));
        ldsm4(Blo[g], base + OFF_BLO + swz64(r, bCh));
    }
#pragma unroll
    for (int i = 0; i < 4; ++i)
#pragma unroll
        for (int j = 0; j < 4; ++j) {
            mma16(c[i][j], Ahi[i], &Bhi[j >> 1][(j & 1) * 2]);
            mma16(c[i][j], Ahi[i], &Blo[j >> 1][(j & 1) * 2]);
        }
    unsigned Alo[4][4];
#pragma unroll
    for (int i = 0; i < 4; ++i)
        ldsm4(Alo[i], base + OFF_ALO + swz64(wm * 64 + i * 16 + aRow, aCh));
#pragma unroll
    for (int i = 0; i < 4; ++i)
#pragma unroll
        for (int j = 0; j < 4; ++j)
            mma16(c[i][j], Alo[i], &Bhi[j >> 1][(j & 1) * 2]);
}

// EPI: 0 = +bias -> fp32 ; 1 = +bias,gelu -> bf16 hi/lo ; 2 = +bias+res, w2o scatter
template <int EPI>
__global__ void __launch_bounds__(256, 2)
gemm_bf16(const u16* __restrict__ Ah, const u16* __restrict__ Al,
          const u16* __restrict__ Bh, const u16* __restrict__ Bl,
          const float* __restrict__ bias, const float* __restrict__ res,
          float* __restrict__ Cf, u16* __restrict__ Ch, u16* __restrict__ Cl,
          int N, int K)
{
    extern __shared__ char sm_raw[];
    unsigned sb = (unsigned)__cvta_generic_to_shared(sm_raw);

    int t = threadIdx.x;
    int warp = t >> 5, lane = t & 31;
    int wm = warp >> 2, wn = warp & 3;
    int bm = blockIdx.y * 128, bn = blockIdx.x * 128;

    float c[4][4][4];
#pragma unroll
    for (int i = 0; i < 4; ++i)
#pragma unroll
        for (int j = 0; j < 4; ++j)
#pragma unroll
            for (int k = 0; k < 4; ++k) c[i][j][k] = 0.f;

    int KT = K >> 5;                     // BK = 32
    load_stage(sb,         Ah, Al, Bh, Bl, K, bm, bn, 0, t);
    asm volatile("cp.async.commit_group;" ::: "memory");
    load_stage(sb + STG32, Ah, Al, Bh, Bl, K, bm, bn, 1, t);
    asm volatile("cp.async.commit_group;" ::: "memory");

    for (int kt = 0; kt < KT; ++kt) {
        if (kt + 1 < KT) asm volatile("cp.async.wait_group 1;" ::: "memory");
        else             asm volatile("cp.async.wait_group 0;" ::: "memory");
        __syncthreads();
        // buffer (kt+2)%3 == (kt-1)%3 was consumed in the previous iteration;
        // the sync above makes its reuse safe.
        if (kt + 2 < KT) {
            load_stage(sb + (unsigned)((kt + 2) % 3) * STG32,
                       Ah, Al, Bh, Bl, K, bm, bn, kt + 2, t);
            asm volatile("cp.async.commit_group;" ::: "memory");
        }
        unsigned base = sb + (unsigned)(kt % 3) * STG32;
        compute_k16(base, 0, wm, wn, lane, c);
        compute_k16(base, 1, wm, wn, lane, c);
    }

    // epilogue (C frag: rows r0,r0+8 ; cols col,col+1)
#pragma unroll
    for (int i = 0; i < 4; ++i) {
        int r0 = bm + wm * 64 + i * 16 + (lane >> 2);
        int rows[2] = { r0, r0 + 8 };
        int dst[2];
        if (EPI == 2) { dst[0] = w2o(rows[0]); dst[1] = w2o(rows[1]); }
#pragma unroll
        for (int j = 0; j < 4; ++j) {
            int col = bn + wn * 32 + j * 8 + ((lane & 3) << 1);
            float bv0 = bias[col], bv1 = bias[col + 1];
#pragma unroll
            for (int rr = 0; rr < 2; ++rr) {
                float v0 = c[i][j][rr * 2 + 0] + bv0;
                float v1 = c[i][j][rr * 2 + 1] + bv1;
                if (EPI == 0) {
                    size_t oo = (size_t)rows[rr] * (size_t)N + col;
                    Cf[oo] = v0; Cf[oo + 1] = v1;
                } else if (EPI == 1) {
                    v0 = gelu_tanh(v0); v1 = gelu_tanh(v1);
                    unsigned h, l; split2(v0, v1, h, l);
                    size_t oo = (size_t)rows[rr] * (size_t)N + col;
                    *reinterpret_cast<unsigned*>(Ch + oo) = h;
                    *reinterpret_cast<unsigned*>(Cl + oo) = l;
                } else {
                    size_t ro = (size_t)rows[rr] * CDIM + col;
                    v0 += res[ro]; v1 += res[ro + 1];
                    size_t oo = (size_t)dst[rr] * CDIM + col;
                    Cf[oo] = v0; Cf[oo + 1] = v1;
                }
            }
        }
    }
}

// ---------------------------------------------------------------------------
// Windowed attention: one CTA per (window, head). fp32 SIMT.
// ---------------------------------------------------------------------------
#define SQ_OFF  0
#define SK_OFF  3136
#define SVT_OFF (3136 + 3528)
#define SP_OFF  (SVT_OFF + 3200)
#define ATTN_SMEM_BYTES ((SP_OFF + 9800) * 4)

__global__ void __launch_bounds__(128)
attn_kernel(const float* __restrict__ qkv, u16* __restrict__ oh, u16* __restrict__ ol)
{
    extern __shared__ float sm[];
    float* sQ  = sm + SQ_OFF;
    float* sK  = sm + SK_OFF;
    float* sVt = sm + SVT_OFF;
    float* sP  = sm + SP_OFF;

    int win  = blockIdx.x >> 4;
    int head = blockIdx.x & 15;
    int t = threadIdx.x, warp = t >> 5, lane = t & 31;

    if (t < 64) sVt[(t >> 1) * 100 + 98 + (t & 1)] = 0.f;

    const float scale = 0.17677669529663687f;
    size_t base = (size_t)win * 98 * QKVDIM + (size_t)head * 32;
    for (int idx = t; idx < 98 * 32; idx += 128) {
        int n = idx >> 5, hd = idx & 31;
        const float* p = qkv + base + (size_t)n * QKVDIM + hd;
        sQ[n * 32 + hd]   = p[0] * scale;
        sK[n * 36 + hd]   = p[512];
        sVt[hd * 100 + n] = p[1024];
    }
    __syncthreads();

    for (int i = warp; i < 98; i += 4) {
        float4 q4[8];
        const float4* qrow = (const float4*)(sQ + i * 32);
#pragma unroll
        for (int cc = 0; cc < 8; ++cc) q4[cc] = qrow[cc];

        float sv[4];
        float mx = -1e30f;
#pragma unroll
        for (int jj = 0; jj < 4; ++jj) {
            int j = lane + jj * 32;
            float a = -1e30f;
            if (j < 98) {
                const float4* krow = (const float4*)(sK + j * 36);
                float acc = 0.f;
#pragma unroll
                for (int cc = 0; cc < 8; ++cc) {
                    float4 k4 = krow[cc];
                    acc += q4[cc].x * k4.x + q4[cc].y * k4.y
                         + q4[cc].z * k4.z + q4[cc].w * k4.w;
                }
                a = acc;
            }
            sv[jj] = a;
            mx = fmaxf(mx, a);
        }
#pragma unroll
        for (int off = 16; off; off >>= 1)
            mx = fmaxf(mx, __shfl_xor_sync(0xffffffffu, mx, off));
        float sum = 0.f;
#pragma unroll
        for (int jj = 0; jj < 4; ++jj) {
            int j = lane + jj * 32;
            float e = (j < 98) ? __expf(sv[jj] - mx) : 0.f;
            sv[jj] = e; sum += e;
        }
#pragma unroll
        for (int off = 16; off; off >>= 1)
            sum += __shfl_xor_sync(0xffffffffu, sum, off);
        float inv = 1.f / sum;
#pragma unroll
        for (int jj = 0; jj < 4; ++jj) {
            int j = lane + jj * 32;
            if (j < 98) sP[i * 100 + j] = sv[jj] * inv;
        }
        if (lane < 2) sP[i * 100 + 98 + lane] = 0.f;
    }
    __syncthreads();

    size_t obase = (size_t)win * 98 * CDIM + (size_t)head * 32 + lane;
    const float4* vrow = (const float4*)(sVt + lane * 100);
    for (int i = warp; i < 98; i += 4) {
        const float4* prow = (const float4*)(sP + i * 100);
        float acc = 0.f;
#pragma unroll
        for (int cc = 0; cc < 25; ++cc) {
            float4 p4 = prow[cc];
            float4 v4 = vrow[cc];
            acc += p4.x * v4.x + p4.y * v4.y + p4.z * v4.z + p4.w * v4.w;
        }
        u16 h, l; split1(acc, h, l);
        oh[obase + (size_t)i * CDIM] = h;
        ol[obase + (size_t)i * CDIM] = l;
    }
}

// ---------------------------------------------------------------------------
// launch
// ---------------------------------------------------------------------------
extern "C" void kernel_launch(void* const* d_in, const int* in_sizes, int n_in,
                              void* d_out, int out_size)
{
    (void)in_sizes; (void)n_in; (void)out_size;

    const float* x     = (const float*)d_in[0];
    const float* g1    = (const float*)d_in[1];
    const float* b1    = (const float*)d_in[2];
    const float* wqkv  = (const float*)d_in[3];
    const float* bqkv  = (const float*)d_in[4];
    const float* wproj = (const float*)d_in[5];
    const float* bproj = (const float*)d_in[6];
    const float* g2    = (const float*)d_in[7];
    const float* b2    = (const float*)d_in[8];
    const float* w1    = (const float*)d_in[9];
    const float* bm1   = (const float*)d_in[10];
    const float* w2    = (const float*)d_in[11];
    const float* bm2   = (const float*)d_in[12];
    float* out = (float*)d_out;

    u16 *hh, *hl, *oh, *ol, *mh, *ml;
    u16 *wqh, *wql, *wph, *wpl, *w1h, *w1l, *w2h, *w2l;
    float *qkv, *attn;
    cudaGetSymbolAddress((void**)&hh,  g_hh);   cudaGetSymbolAddress((void**)&hl,  g_hl);
    cudaGetSymbolAddress((void**)&qkv, g_qkv);
    cudaGetSymbolAddress((void**)&oh,  g_oh);   cudaGetSymbolAddress((void**)&ol,  g_ol);
    cudaGetSymbolAddress((void**)&attn,g_attn);
    cudaGetSymbolAddress((void**)&mh,  g_mh);   cudaGetSymbolAddress((void**)&ml,  g_ml);
    cudaGetSymbolAddress((void**)&wqh, g_wqkvh); cudaGetSymbolAddress((void**)&wql, g_wqkvl);
    cudaGetSymbolAddress((void**)&wph, g_wprh);  cudaGetSymbolAddress((void**)&wpl, g_wprl);
    cudaGetSymbolAddress((void**)&w1h, g_w1h);   cudaGetSymbolAddress((void**)&w1l, g_w1l);
    cudaGetSymbolAddress((void**)&w2h, g_w2h);   cudaGetSymbolAddress((void**)&w2l, g_w2l);

    cudaFuncSetAttribute((const void*)attn_kernel,
                         cudaFuncAttributeMaxDynamicSharedMemorySize, ATTN_SMEM_BYTES);
    cudaFuncSetAttribute((const void*)gemm_bf16<0>,
                         cudaFuncAttributeMaxDynamicSharedMemorySize, GEMM_DSM);
    cudaFuncSetAttribute((const void*)gemm_bf16<1>,
                         cudaFuncAttributeMaxDynamicSharedMemorySize, GEMM_DSM);
    cudaFuncSetAttribute((const void*)gemm_bf16<2>,
                         cudaFuncAttributeMaxDynamicSharedMemorySize, GEMM_DSM);

    dim3 wblk(32, 8);
    wconv_kernel<<<dim3(QKVDIM / 32, CDIM / 32), wblk>>>(wqkv, wqh, wql, CDIM, QKVDIM);
    wconv_kernel<<<dim3(CDIM / 32, CDIM / 32),   wblk>>>(wproj, wph, wpl, CDIM, CDIM);
    wconv_kernel<<<dim3(MLPDIM / 32, CDIM / 32), wblk>>>(w1, w1h, w1l, CDIM, MLPDIM);
    wconv_kernel<<<dim3(CDIM / 32, MLPDIM / 32), wblk>>>(w2, w2h, w2l, MLPDIM, CDIM);

    const int LN_BLOCKS = TOKENS / 8;
    const int MT = TOKENS / 128;   // 784

    // 1. window-partition gather + LN1
    ln_kernel<<<LN_BLOCKS, 256>>>(x, g1, b1, hh, hl, 1);

    // 2. qkv = h @ wqkv + bqkv (fp32)
    gemm_bf16<0><<<dim3(QKVDIM / 128, MT), 256, GEMM_DSM>>>(
        hh, hl, wqh, wql, bqkv, nullptr, qkv, nullptr, nullptr, QKVDIM, CDIM);

    // 3. windowed attention
    attn_kernel<<<NWINHEAD, 128, ATTN_SMEM_BYTES>>>(qkv, oh, ol);

    // 4. attn = o @ wproj + bproj (fp32)
    gemm_bf16<0><<<dim3(CDIM / 128, MT), 256, GEMM_DSM>>>(
        oh, ol, wph, wpl, bproj, nullptr, attn, nullptr, nullptr, CDIM, CDIM);

    // 5. LN2
    ln_kernel<<<LN_BLOCKS, 256>>>(attn, g2, b2, hh, hl, 0);

    // 6. hidden = gelu(h @ w1 + bm1) (bf16 hi/lo)
    gemm_bf16<1><<<dim3(MLPDIM / 128, MT), 256, GEMM_DSM>>>(
        hh, hl, w1h, w1l, bm1, nullptr, nullptr, mh, ml, MLPDIM, CDIM);

    // 7. out[w2o(m)] = attn[m] + hidden[m] @ w2 + bm2
    gemm_bf16<2><<<dim3(CDIM / 128, MT), 256, GEMM_DSM>>>(
        mh, ml, w2h, w2l, bm2, attn, out, nullptr, nullptr, CDIM, MLPDIM);
}